// round 13
// baseline (speedup 1.0000x reference)
#include <cuda_runtime.h>

#define S   2048
#define F   512
#define B   32
#define RAD 12
#define KW  25
#define NTILES (S / 32)   // 64 row-tiles

// ---------------- scratch (device globals: no allocations allowed) ----------
__device__ int   g_i0[S];
__device__ float g_frac[S];
__device__ int   g_slo[NTILES];   // first s whose i0 falls in tile
__device__ int   g_scnt[NTILES];  // number of such s

// Gaussian taps (sigma=3, radius=12, normalized) — compile-time immediates
// (fully-unrolled loops index this with constants; ptxas folds to FFMA-imm, rt=1).
__device__ constexpr float KERN[KW] = {
    4.46116e-05f, 1.60100e-04f, 5.14120e-04f, 1.47730e-03f, 3.79880e-03f,
    8.74080e-03f, 1.799760e-02f, 3.316010e-02f, 5.467130e-02f, 8.065920e-02f,
    1.0648560e-01f, 1.2579790e-01f, 1.3298450e-01f, 1.2579790e-01f, 1.0648560e-01f,
    8.065920e-02f, 5.467130e-02f, 3.316010e-02f, 1.799760e-02f, 8.74080e-03f,
    3.79880e-03f, 1.47730e-03f, 5.14120e-04f, 1.60100e-04f, 4.46116e-05f
};

__device__ __forceinline__ int reflect_idx(int r) {
    if (r < 0)       r = -1 - r;
    else if (r >= S) r = 2 * S - 1 - r;
    return r;
}

// ---------------- kernel A: warp precompute + loss (1 block, 256 thr) -------
// Numerics mirror the jax reference bitwise where it matters (see R5):
//  * tt = iota * fl(1/2047); no FMA contraction; sequential ascending dot
//  * softplus = max(w,0) + log1p(exp(-|w|))
//  * cumsum = jax associative_scan pairwise tree (exact rounding pattern)
#define WT 256
__global__ void __launch_bounds__(WT) warp_precompute_kernel(
        const float* __restrict__ W1,
        const float* __restrict__ b1,
        const float* __restrict__ W2,
        const float* __restrict__ b2,
        float* __restrict__ out_loss) {
    __shared__ float lev[4095];   // levels 0..11 of the scan tree
    __shared__ float warps[S];
    __shared__ int   si0[S];
    __shared__ float red[WT];
    __shared__ float sW1[64], sB1[64], sW2[64];
    __shared__ float sB2;

    const int t = threadIdx.x;

    if (t < 64) { sW1[t] = W1[t]; sB1[t] = b1[t]; sW2[t] = W2[t]; }
    if (t == 64) sB2 = b2[0];
    __syncthreads();

    int off[12];
    {
        int o = 0;
        #pragma unroll
        for (int l = 0; l < 12; l++) { off[l] = o; o += (2048 >> l); }
    }

    // ---- elementwise: 8 s-positions per thread, interleaved chains ----
    {
        const float delta = 1.0f / 2047.0f;
        float tt[8], acc[8];
        #pragma unroll
        for (int u = 0; u < 8; u++) {
            int s = t + u * WT;
            tt[u]  = (s == S - 1) ? 1.0f : __fmul_rn((float)s, delta);
            acc[u] = 0.0f;
        }
        for (int j = 0; j < 64; j++) {
            const float w1 = sW1[j], bb = sB1[j], w2 = sW2[j];
            #pragma unroll
            for (int u = 0; u < 8; u++) {
                float h = __fadd_rn(__fmul_rn(tt[u], w1), bb);
                h = fmaxf(h, 0.0f);
                acc[u] = __fadd_rn(acc[u], __fmul_rn(h, w2));
            }
        }
        #pragma unroll
        for (int u = 0; u < 8; u++) {
            float w  = tanhf(__fadd_rn(acc[u], sB2));
            float sp = __fadd_rn(fmaxf(w, 0.0f), log1pf(expf(-fabsf(w))));
            lev[off[0] + t + u * WT] = sp;
        }
    }

    for (int l = 0; l < 11; l++) {
        __syncthreads();
        const float* src = lev + off[l];
        float*       dst = lev + off[l + 1];
        const int n_next = 2048 >> (l + 1);
        for (int k = t; k < n_next; k += WT)
            dst[k] = __fadd_rn(src[2 * k], src[2 * k + 1]);
    }
    __syncthreads();

    for (int l = 10; l >= 0; l--) {
        float*       Ll  = lev + off[l];
        const float* Sl1 = lev + off[l + 1];
        const int half = 2048 >> (l + 1);
        for (int k = t; k < half; k += WT) {
            float odd_val  = Sl1[k];
            float even_val = (k == 0) ? Ll[0] : __fadd_rn(Sl1[k - 1], Ll[2 * k]);
            Ll[2 * k]     = even_val;
            Ll[2 * k + 1] = odd_val;
        }
        __syncthreads();
    }

    const float T = lev[S - 1];

    for (int s = t; s < S; s += WT)
        warps[s] = __fdiv_rn(lev[s], T);
    __syncthreads();

    for (int s = t; s < S; s += WT) {
        float pos = __fmul_rn(warps[s], (float)(S - 1));
        float fi  = floorf(pos);
        fi = fminf(fmaxf(fi, 0.0f), (float)(S - 2));
        int i0 = (int)fi;
        g_i0[s]   = i0;
        si0[s]    = i0;
        g_frac[s] = __fadd_rn(pos, -fi);
    }
    __syncthreads();

    // per-row-tile output ranges: tile t owns s with i0 in [32t, 32t+31]
    if (t < NTILES) {
        int lo_val = 32 * t;
        // lower_bound(si0, lo_val)
        int a = 0, bnd = S;
        while (a < bnd) { int m = (a + bnd) >> 1; if (si0[m] < lo_val) a = m + 1; else bnd = m; }
        int s_lo = a;
        int hi_val = lo_val + 32;
        a = s_lo; bnd = S;
        while (a < bnd) { int m = (a + bnd) >> 1; if (si0[m] < hi_val) a = m + 1; else bnd = m; }
        g_slo[t]  = s_lo;
        g_scnt[t] = a - s_lo;
    }

    float lsum = 0.0f;
    for (int m = t; m < S - 2; m += WT) {
        float d1a = __fadd_rn(warps[m + 1], -warps[m]);
        float d1b = __fadd_rn(warps[m + 2], -warps[m + 1]);
        float d2  = __fadd_rn(d1b, -d1a);
        lsum = fmaf(d2, d2, lsum);
    }
    red[t] = lsum;
    __syncthreads();
    for (int o2 = WT / 2; o2 > 0; o2 >>= 1) {
        if (t < o2) red[t] += red[t + o2];
        __syncthreads();
    }
    if (t == 0) *out_loss = red[0] / (float)(S - 2);
}

// ---------------- fused smooth + interp (row-tiled, uniform work) -----------
// Block = 256 threads = 4 quarters x 64 f-lanes. Block owns smoothed rows
// [r0, r0+32] (33 rows: quarters 0-2 compute 8 rows, quarter 3 computes 9).
// Uniform conv work across all blocks; outputs s with i0 in the tile are
// interpolated from the 8.25KB static smem stage and written directly.

#define FL 64

template<int CHT>
__device__ __forceinline__ void conv_rows_fast(const float* __restrict__ p,
                                               float* __restrict__ dst) {
    constexpr int NVT = CHT + KW - 1;
    float v[NVT];
    #pragma unroll
    for (int i = 0; i < NVT; i++) v[i] = __ldg(p + i * F);   // imm offsets
    float acc[CHT];
    #pragma unroll
    for (int j = 0; j < CHT; j++) acc[j] = 0.0f;
    #pragma unroll
    for (int i = 0; i < NVT; i++) {
        #pragma unroll
        for (int j = 0; j < CHT; j++) {
            const int k = i - j;
            if (k >= 0 && k < KW)
                acc[j] = fmaf(v[i], KERN[k], acc[j]);
        }
    }
    #pragma unroll
    for (int j = 0; j < CHT; j++) dst[j * FL] = acc[j];
}

template<int CHT>
__device__ __forceinline__ void conv_rows_refl(const float* __restrict__ xb,
                                               int c0,
                                               float* __restrict__ dst) {
    constexpr int NVT = CHT + KW - 1;
    float v[NVT];
    #pragma unroll
    for (int i = 0; i < NVT; i++)
        v[i] = __ldg(xb + (size_t)reflect_idx(c0 - RAD + i) * F);
    float acc[CHT];
    #pragma unroll
    for (int j = 0; j < CHT; j++) acc[j] = 0.0f;
    #pragma unroll
    for (int i = 0; i < NVT; i++) {
        #pragma unroll
        for (int j = 0; j < CHT; j++) {
            const int k = i - j;
            if (k >= 0 && k < KW)
                acc[j] = fmaf(v[i], KERN[k], acc[j]);
        }
    }
    #pragma unroll
    for (int j = 0; j < CHT; j++) dst[j * FL] = acc[j];
}

__global__ void __launch_bounds__(256, 5) fused_kernel(const float* __restrict__ x,
                                                       float* __restrict__ out) {
    __shared__ float smrows[33 * FL];   // 8448 B

    const int tx      = threadIdx.x;
    const int lane    = tx & (FL - 1);
    const int quarter = tx >> 6;        // 0..3
    const int r0 = blockIdx.x * 32;
    const int f0 = blockIdx.y * FL;
    const int b  = blockIdx.z;

    const float* xb = x + (size_t)b * (S * F) + f0 + lane;
    const int rq = r0 + quarter * 8;              // first smoothed row of my chunk
    float* dst = smrows + quarter * 8 * FL + lane;

    const bool interior = (blockIdx.x != 0) && (blockIdx.x != gridDim.x - 1);
    if (interior) {
        const float* p = xb + (size_t)(rq - RAD) * F;
        if (quarter < 3) conv_rows_fast<8>(p, dst);
        else             conv_rows_fast<9>(p, dst);
    } else {
        if (quarter < 3) conv_rows_refl<8>(xb, rq, dst);
        else             conv_rows_refl<9>(xb, rq, dst);
    }
    __syncthreads();

    // interp: outputs s with i0 in [r0, r0+31]; float4 over FL
    const int s_lo = g_slo[blockIdx.x];
    const int cnt  = g_scnt[blockIdx.x];
    const int nunits = cnt * (FL / 4);
    for (int u = tx; u < nunits; u += 256) {
        const int s    = s_lo + (u >> 4);
        const int col4 = u & 15;
        const int ro   = __ldg(g_i0 + s) - r0;
        const float fr = __ldg(g_frac + s);
        const float om = 1.0f - fr;

        const float4 a = ((const float4*)(smrows + ro * FL))[col4];
        const float4 c = ((const float4*)(smrows + (ro + 1) * FL))[col4];
        float4 o;
        o.x = a.x * om + c.x * fr;
        o.y = a.y * om + c.y * fr;
        o.z = a.z * om + c.z * fr;
        o.w = a.w * om + c.w * fr;
        ((float4*)(out + ((size_t)(b * S + s) * F + f0)))[col4] = o;
    }
}

// ---------------- launch ----------------------------------------------------
extern "C" void kernel_launch(void* const* d_in, const int* in_sizes, int n_in,
                              void* d_out, int out_size) {
    const float* x  = (const float*)d_in[0];
    const float* W1 = (const float*)d_in[1];
    const float* b1 = (const float*)d_in[2];
    const float* W2 = (const float*)d_in[3];
    const float* b2 = (const float*)d_in[4];
    float* out = (float*)d_out;

    // loss scalar is the last output element
    warp_precompute_kernel<<<1, WT>>>(W1, b1, W2, b2, out + (out_size - 1));

    dim3 gridF(NTILES, F / FL, B);
    fused_kernel<<<gridF, 256>>>(x, out);
}

// round 15
// speedup vs baseline: 1.0508x; 1.0508x over previous
#include <cuda_runtime.h>

#define S   2048
#define F   512
#define B   32
#define RAD 12
#define KW  25
#define NTILES (S / 32)   // 64 row-tiles

// ---------------- scratch (device globals: no allocations allowed) ----------
__device__ float g_sp[S];         // softplus(tanh(MLP)) per s
__device__ int   g_i0[S];
__device__ float g_frac[S];
__device__ int   g_slo[NTILES];   // first s whose i0 falls in tile
__device__ int   g_scnt[NTILES];  // number of such s

// Gaussian taps (sigma=3, radius=12, normalized) — compile-time immediates
// (fully-unrolled loops index this with constants; ptxas folds to FFMA-imm, rt=1).
__device__ constexpr float KERN[KW] = {
    4.46116e-05f, 1.60100e-04f, 5.14120e-04f, 1.47730e-03f, 3.79880e-03f,
    8.74080e-03f, 1.799760e-02f, 3.316010e-02f, 5.467130e-02f, 8.065920e-02f,
    1.0648560e-01f, 1.2579790e-01f, 1.3298450e-01f, 1.2579790e-01f, 1.0648560e-01f,
    8.065920e-02f, 5.467130e-02f, 3.316010e-02f, 1.799760e-02f, 8.74080e-03f,
    3.79880e-03f, 1.47730e-03f, 5.14120e-04f, 1.60100e-04f, 4.46116e-05f
};

__device__ __forceinline__ int reflect_idx(int r) {
    if (r < 0)       r = -1 - r;
    else if (r >= S) r = 2 * S - 1 - r;
    return r;
}

// ---------------- kernel A0: MLP + softplus, parallel across 16 blocks ------
// Per-s FP op chain is IDENTICAL to previous rounds (bitwise-same g_sp).
__global__ void __launch_bounds__(128) mlp_kernel(
        const float* __restrict__ W1,
        const float* __restrict__ b1,
        const float* __restrict__ W2,
        const float* __restrict__ b2) {
    __shared__ float sW1[64], sB1[64], sW2[64];
    __shared__ float sB2;
    const int t = threadIdx.x;
    if (t < 64) { sW1[t] = W1[t]; sB1[t] = b1[t]; sW2[t] = W2[t]; }
    if (t == 64) sB2 = b2[0];
    __syncthreads();

    const int s = blockIdx.x * 128 + t;
    const float delta = 1.0f / 2047.0f;
    float tt = (s == S - 1) ? 1.0f : __fmul_rn((float)s, delta);
    float acc = 0.0f;
    for (int j = 0; j < 64; j++) {
        float h = __fadd_rn(__fmul_rn(tt, sW1[j]), sB1[j]);
        h = fmaxf(h, 0.0f);
        acc = __fadd_rn(acc, __fmul_rn(h, sW2[j]));
    }
    float w  = tanhf(__fadd_rn(acc, sB2));
    g_sp[s]  = __fadd_rn(fmaxf(w, 0.0f), log1pf(expf(-fabsf(w))));
}

// ---------------- kernel A1: scan + tables + loss (1 block, 256 thr) --------
// cumsum = jax associative_scan pairwise tree (exact rounding pattern, see R5).
#define WT 256
__global__ void __launch_bounds__(WT) scan_kernel(float* __restrict__ out_loss) {
    __shared__ float lev[4095];   // levels 0..11 of the scan tree
    __shared__ float warps[S];
    __shared__ int   si0[S];
    __shared__ float red[WT];

    const int t = threadIdx.x;

    int off[12];
    {
        int o = 0;
        #pragma unroll
        for (int l = 0; l < 12; l++) { off[l] = o; o += (2048 >> l); }
    }

    for (int s = t; s < S; s += WT) lev[off[0] + s] = g_sp[s];

    for (int l = 0; l < 11; l++) {
        __syncthreads();
        const float* src = lev + off[l];
        float*       dst = lev + off[l + 1];
        const int n_next = 2048 >> (l + 1);
        for (int k = t; k < n_next; k += WT)
            dst[k] = __fadd_rn(src[2 * k], src[2 * k + 1]);
    }
    __syncthreads();

    for (int l = 10; l >= 0; l--) {
        float*       Ll  = lev + off[l];
        const float* Sl1 = lev + off[l + 1];
        const int half = 2048 >> (l + 1);
        for (int k = t; k < half; k += WT) {
            float odd_val  = Sl1[k];
            float even_val = (k == 0) ? Ll[0] : __fadd_rn(Sl1[k - 1], Ll[2 * k]);
            Ll[2 * k]     = even_val;
            Ll[2 * k + 1] = odd_val;
        }
        __syncthreads();
    }

    const float T = lev[S - 1];

    for (int s = t; s < S; s += WT)
        warps[s] = __fdiv_rn(lev[s], T);
    __syncthreads();

    for (int s = t; s < S; s += WT) {
        float pos = __fmul_rn(warps[s], (float)(S - 1));
        float fi  = floorf(pos);
        fi = fminf(fmaxf(fi, 0.0f), (float)(S - 2));
        int i0 = (int)fi;
        g_i0[s]   = i0;
        si0[s]    = i0;
        g_frac[s] = __fadd_rn(pos, -fi);
    }
    __syncthreads();

    // per-row-tile output ranges: tile t owns s with i0 in [32t, 32t+31]
    if (t < NTILES) {
        int lo_val = 32 * t;
        int a = 0, bnd = S;
        while (a < bnd) { int m = (a + bnd) >> 1; if (si0[m] < lo_val) a = m + 1; else bnd = m; }
        int s_lo = a;
        int hi_val = lo_val + 32;
        a = s_lo; bnd = S;
        while (a < bnd) { int m = (a + bnd) >> 1; if (si0[m] < hi_val) a = m + 1; else bnd = m; }
        g_slo[t]  = s_lo;
        g_scnt[t] = a - s_lo;
    }

    float lsum = 0.0f;
    for (int m = t; m < S - 2; m += WT) {
        float d1a = __fadd_rn(warps[m + 1], -warps[m]);
        float d1b = __fadd_rn(warps[m + 2], -warps[m + 1]);
        float d2  = __fadd_rn(d1b, -d1a);
        lsum = fmaf(d2, d2, lsum);
    }
    red[t] = lsum;
    __syncthreads();
    for (int o2 = WT / 2; o2 > 0; o2 >>= 1) {
        if (t < o2) red[t] += red[t + o2];
        __syncthreads();
    }
    if (t == 0) *out_loss = red[0] / (float)(S - 2);
}

// ---------------- fused smooth + interp (row-tiled, uniform work) -----------
// Block = 256 threads = 4 quarters x 64 f-lanes, owns smoothed rows
// [r0, r0+32]. Interp metadata is prefetched into smem BEFORE the conv phase
// so the post-barrier interp is LDS-only (no cold LDG stall).

#define FL 64
#define MAXCNT 144   // > theoretical max outputs per tile (~136)

template<int CHT>
__device__ __forceinline__ void conv_rows_fast(const float* __restrict__ p,
                                               float* __restrict__ dst) {
    constexpr int NVT = CHT + KW - 1;
    float v[NVT];
    #pragma unroll
    for (int i = 0; i < NVT; i++) v[i] = __ldg(p + i * F);   // imm offsets
    float acc[CHT];
    #pragma unroll
    for (int j = 0; j < CHT; j++) acc[j] = 0.0f;
    #pragma unroll
    for (int i = 0; i < NVT; i++) {
        #pragma unroll
        for (int j = 0; j < CHT; j++) {
            const int k = i - j;
            if (k >= 0 && k < KW)
                acc[j] = fmaf(v[i], KERN[k], acc[j]);
        }
    }
    #pragma unroll
    for (int j = 0; j < CHT; j++) dst[j * FL] = acc[j];
}

template<int CHT>
__device__ __forceinline__ void conv_rows_refl(const float* __restrict__ xb,
                                               int c0,
                                               float* __restrict__ dst) {
    constexpr int NVT = CHT + KW - 1;
    float v[NVT];
    #pragma unroll
    for (int i = 0; i < NVT; i++)
        v[i] = __ldg(xb + (size_t)reflect_idx(c0 - RAD + i) * F);
    float acc[CHT];
    #pragma unroll
    for (int j = 0; j < CHT; j++) acc[j] = 0.0f;
    #pragma unroll
    for (int i = 0; i < NVT; i++) {
        #pragma unroll
        for (int j = 0; j < CHT; j++) {
            const int k = i - j;
            if (k >= 0 && k < KW)
                acc[j] = fmaf(v[i], KERN[k], acc[j]);
        }
    }
    #pragma unroll
    for (int j = 0; j < CHT; j++) dst[j * FL] = acc[j];
}

__global__ void __launch_bounds__(256, 5) fused_kernel(const float* __restrict__ x,
                                                       float* __restrict__ out) {
    __shared__ float smrows[33 * FL];   // 8448 B
    __shared__ int   sm_ro[MAXCNT];     // i0 - r0 per output
    __shared__ float sm_fr[MAXCNT];

    const int tx      = threadIdx.x;
    const int lane    = tx & (FL - 1);
    const int quarter = tx >> 6;        // 0..3
    const int r0 = blockIdx.x * 32;
    const int f0 = blockIdx.y * FL;
    const int b  = blockIdx.z;

    const int s_lo = g_slo[blockIdx.x];
    const int cnt  = g_scnt[blockIdx.x];

    // prefetch interp metadata (completes during conv phase)
    for (int u = tx; u < cnt; u += 256) {
        sm_ro[u] = __ldg(g_i0 + s_lo + u) - r0;
        sm_fr[u] = __ldg(g_frac + s_lo + u);
    }

    const float* xb = x + (size_t)b * (S * F) + f0 + lane;
    const int rq = r0 + quarter * 8;              // first smoothed row of my chunk
    float* dst = smrows + quarter * 8 * FL + lane;

    const bool interior = (blockIdx.x != 0) && (blockIdx.x != gridDim.x - 1);
    if (interior) {
        const float* p = xb + (size_t)(rq - RAD) * F;
        if (quarter < 3) conv_rows_fast<8>(p, dst);
        else             conv_rows_fast<9>(p, dst);
    } else {
        if (quarter < 3) conv_rows_refl<8>(xb, rq, dst);
        else             conv_rows_refl<9>(xb, rq, dst);
    }
    __syncthreads();

    // interp: outputs s with i0 in [r0, r0+31]; float4 over FL; LDS-only reads
    const int nunits = cnt * (FL / 4);
    for (int u = tx; u < nunits; u += 256) {
        const int ui   = u >> 4;
        const int s    = s_lo + ui;
        const int col4 = u & 15;
        const int ro   = sm_ro[ui];
        const float fr = sm_fr[ui];
        const float om = 1.0f - fr;

        const float4 a = ((const float4*)(smrows + ro * FL))[col4];
        const float4 c = ((const float4*)(smrows + (ro + 1) * FL))[col4];
        float4 o;
        o.x = a.x * om + c.x * fr;
        o.y = a.y * om + c.y * fr;
        o.z = a.z * om + c.z * fr;
        o.w = a.w * om + c.w * fr;
        ((float4*)(out + ((size_t)(b * S + s) * F + f0)))[col4] = o;
    }
}

// ---------------- launch ----------------------------------------------------
extern "C" void kernel_launch(void* const* d_in, const int* in_sizes, int n_in,
                              void* d_out, int out_size) {
    const float* x  = (const float*)d_in[0];
    const float* W1 = (const float*)d_in[1];
    const float* b1 = (const float*)d_in[2];
    const float* W2 = (const float*)d_in[3];
    const float* b2 = (const float*)d_in[4];
    float* out = (float*)d_out;

    mlp_kernel<<<S / 128, 128>>>(W1, b1, W2, b2);
    // loss scalar is the last output element
    scan_kernel<<<1, WT>>>(out + (out_size - 1));

    dim3 gridF(NTILES, F / FL, B);
    fused_kernel<<<gridF, 256>>>(x, out);
}

// round 16
// speedup vs baseline: 1.3130x; 1.2495x over previous
#include <cuda_runtime.h>

#define S   2048
#define F   512
#define B   32
#define RAD 12
#define KW  25
#define NTILES (S / 32)   // 64 row-tiles

typedef unsigned long long ull;

// ---------------- scratch (device globals: no allocations allowed) ----------
__device__ float g_sp[S];         // softplus(tanh(MLP)) per s
__device__ int   g_i0[S];
__device__ float g_frac[S];
__device__ int   g_slo[NTILES];   // first s whose i0 falls in tile
__device__ int   g_scnt[NTILES];  // number of such s

// Gaussian taps (sigma=3, radius=12, normalized)
__device__ constexpr float KERN[KW] = {
    4.46116e-05f, 1.60100e-04f, 5.14120e-04f, 1.47730e-03f, 3.79880e-03f,
    8.74080e-03f, 1.799760e-02f, 3.316010e-02f, 5.467130e-02f, 8.065920e-02f,
    1.0648560e-01f, 1.2579790e-01f, 1.3298450e-01f, 1.2579790e-01f, 1.0648560e-01f,
    8.065920e-02f, 5.467130e-02f, 3.316010e-02f, 1.799760e-02f, 8.74080e-03f,
    3.79880e-03f, 1.47730e-03f, 5.14120e-04f, 1.60100e-04f, 4.46116e-05f
};

__device__ __forceinline__ int reflect_idx(int r) {
    if (r < 0)       r = -1 - r;
    else if (r >= S) r = 2 * S - 1 - r;
    return r;
}

// packed-pair helpers (each half is IEEE fma.rn — bitwise == scalar fmaf)
__device__ __forceinline__ ull pack_tap(float k) {
    ull t; asm("mov.b64 %0, {%1, %1};" : "=l"(t) : "f"(k)); return t;
}
__device__ __forceinline__ void fma2(ull& a, ull v, ull t) {
    asm("fma.rn.f32x2 %0, %1, %2, %0;" : "+l"(a) : "l"(v), "l"(t));
}

// ---------------- kernel A0: MLP + softplus, parallel across 16 blocks ------
__global__ void __launch_bounds__(128) mlp_kernel(
        const float* __restrict__ W1,
        const float* __restrict__ b1,
        const float* __restrict__ W2,
        const float* __restrict__ b2) {
    __shared__ float sW1[64], sB1[64], sW2[64];
    __shared__ float sB2;
    const int t = threadIdx.x;
    if (t < 64) { sW1[t] = W1[t]; sB1[t] = b1[t]; sW2[t] = W2[t]; }
    if (t == 64) sB2 = b2[0];
    __syncthreads();

    const int s = blockIdx.x * 128 + t;
    const float delta = 1.0f / 2047.0f;
    float tt = (s == S - 1) ? 1.0f : __fmul_rn((float)s, delta);
    float acc = 0.0f;
    for (int j = 0; j < 64; j++) {
        float h = __fadd_rn(__fmul_rn(tt, sW1[j]), sB1[j]);
        h = fmaxf(h, 0.0f);
        acc = __fadd_rn(acc, __fmul_rn(h, sW2[j]));
    }
    float w  = tanhf(__fadd_rn(acc, sB2));
    g_sp[s]  = __fadd_rn(fmaxf(w, 0.0f), log1pf(expf(-fabsf(w))));
}

// ---------------- kernel A1: scan + tables + loss (1 block, 256 thr) --------
#define WT 256
__global__ void __launch_bounds__(WT) scan_kernel(float* __restrict__ out_loss) {
    __shared__ float lev[4095];
    __shared__ float warps[S];
    __shared__ int   si0[S];
    __shared__ float red[WT];

    const int t = threadIdx.x;

    int off[12];
    {
        int o = 0;
        #pragma unroll
        for (int l = 0; l < 12; l++) { off[l] = o; o += (2048 >> l); }
    }

    for (int s = t; s < S; s += WT) lev[off[0] + s] = g_sp[s];

    for (int l = 0; l < 11; l++) {
        __syncthreads();
        const float* src = lev + off[l];
        float*       dst = lev + off[l + 1];
        const int n_next = 2048 >> (l + 1);
        for (int k = t; k < n_next; k += WT)
            dst[k] = __fadd_rn(src[2 * k], src[2 * k + 1]);
    }
    __syncthreads();

    for (int l = 10; l >= 0; l--) {
        float*       Ll  = lev + off[l];
        const float* Sl1 = lev + off[l + 1];
        const int half = 2048 >> (l + 1);
        for (int k = t; k < half; k += WT) {
            float odd_val  = Sl1[k];
            float even_val = (k == 0) ? Ll[0] : __fadd_rn(Sl1[k - 1], Ll[2 * k]);
            Ll[2 * k]     = even_val;
            Ll[2 * k + 1] = odd_val;
        }
        __syncthreads();
    }

    const float T = lev[S - 1];

    for (int s = t; s < S; s += WT)
        warps[s] = __fdiv_rn(lev[s], T);
    __syncthreads();

    for (int s = t; s < S; s += WT) {
        float pos = __fmul_rn(warps[s], (float)(S - 1));
        float fi  = floorf(pos);
        fi = fminf(fmaxf(fi, 0.0f), (float)(S - 2));
        int i0 = (int)fi;
        g_i0[s]   = i0;
        si0[s]    = i0;
        g_frac[s] = __fadd_rn(pos, -fi);
    }
    __syncthreads();

    if (t < NTILES) {
        int lo_val = 32 * t;
        int a = 0, bnd = S;
        while (a < bnd) { int m = (a + bnd) >> 1; if (si0[m] < lo_val) a = m + 1; else bnd = m; }
        int s_lo = a;
        int hi_val = lo_val + 32;
        a = s_lo; bnd = S;
        while (a < bnd) { int m = (a + bnd) >> 1; if (si0[m] < hi_val) a = m + 1; else bnd = m; }
        g_slo[t]  = s_lo;
        g_scnt[t] = a - s_lo;
    }

    float lsum = 0.0f;
    for (int m = t; m < S - 2; m += WT) {
        float d1a = __fadd_rn(warps[m + 1], -warps[m]);
        float d1b = __fadd_rn(warps[m + 2], -warps[m + 1]);
        float d2  = __fadd_rn(d1b, -d1a);
        lsum = fmaf(d2, d2, lsum);
    }
    red[t] = lsum;
    __syncthreads();
    for (int o2 = WT / 2; o2 > 0; o2 >>= 1) {
        if (t < o2) red[t] += red[t + o2];
        __syncthreads();
    }
    if (t == 0) *out_loss = red[0] / (float)(S - 2);
}

// ---------------- fused smooth + interp (f32x2, row-tiled) ------------------
// Block = 256 thr = 4 quarters x 64 lanes; each lane owns 2 consecutive f
// (FL = 128 f per block). Quarters compute 8/8/8/9 smoothed rows of
// [r0, r0+32] with packed fma.rn.f32x2 (k-outer tap loop, sliding input
// window), staged in 16.9KB smem; interp reads smem, writes float4.

#define FL 128
#define MAXCNT 144

template<int CHT>
__device__ __forceinline__ void conv2_fast(const char* __restrict__ pbase,
                                           float* __restrict__ dst) {
    constexpr int NVT = CHT + KW - 1;
    ull vv[NVT];
    #pragma unroll
    for (int i = 0; i < CHT; i++)
        vv[i] = *(const ull*)(pbase + (size_t)i * (F * 4));
    ull acc[CHT];
    #pragma unroll
    for (int j = 0; j < CHT; j++) acc[j] = 0ULL;

    #pragma unroll
    for (int m = 0; m < KW; m++) {
        if (m + CHT < NVT)
            vv[m + CHT] = *(const ull*)(pbase + (size_t)(m + CHT) * (F * 4));
        const ull tap = pack_tap(KERN[m]);
        #pragma unroll
        for (int j = 0; j < CHT; j++) fma2(acc[j], vv[m + j], tap);
    }
    #pragma unroll
    for (int j = 0; j < CHT; j++)
        *(ull*)(dst + j * FL) = acc[j];
}

template<int CHT>
__device__ __forceinline__ void conv2_refl(const char* __restrict__ xb,
                                           int c0,
                                           float* __restrict__ dst) {
    constexpr int NVT = CHT + KW - 1;
    ull vv[NVT];
    #pragma unroll
    for (int i = 0; i < CHT; i++)
        vv[i] = *(const ull*)(xb + (size_t)reflect_idx(c0 - RAD + i) * (F * 4));
    ull acc[CHT];
    #pragma unroll
    for (int j = 0; j < CHT; j++) acc[j] = 0ULL;

    #pragma unroll
    for (int m = 0; m < KW; m++) {
        if (m + CHT < NVT)
            vv[m + CHT] = *(const ull*)(xb + (size_t)reflect_idx(c0 - RAD + m + CHT) * (F * 4));
        const ull tap = pack_tap(KERN[m]);
        #pragma unroll
        for (int j = 0; j < CHT; j++) fma2(acc[j], vv[m + j], tap);
    }
    #pragma unroll
    for (int j = 0; j < CHT; j++)
        *(ull*)(dst + j * FL) = acc[j];
}

__global__ void __launch_bounds__(256, 5) fused_kernel(const float* __restrict__ x,
                                                       float* __restrict__ out) {
    __shared__ float smrows[33 * FL];   // 16896 B
    __shared__ int   sm_ro[MAXCNT];
    __shared__ float sm_fr[MAXCNT];

    const int tx      = threadIdx.x;
    const int lane    = tx & 63;        // 8-byte column within 128-f row
    const int quarter = tx >> 6;        // 0..3
    const int r0 = blockIdx.x * 32;
    const int f0 = blockIdx.y * FL;
    const int b  = blockIdx.z;

    const int s_lo = g_slo[blockIdx.x];
    const int cnt  = g_scnt[blockIdx.x];

    // prefetch interp metadata (completes during conv phase)
    for (int u = tx; u < cnt; u += 256) {
        sm_ro[u] = __ldg(g_i0 + s_lo + u) - r0;
        sm_fr[u] = __ldg(g_frac + s_lo + u);
    }

    const char* xb = (const char*)(x + (size_t)b * (S * F) + f0 + lane * 2);
    const int rq = r0 + quarter * 8;
    float* dst = smrows + quarter * 8 * FL + lane * 2;

    const bool interior = (blockIdx.x != 0) && (blockIdx.x != gridDim.x - 1);
    if (interior) {
        const char* p = xb + (size_t)(rq - RAD) * (F * 4);
        if (quarter < 3) conv2_fast<8>(p, dst);
        else             conv2_fast<9>(p, dst);
    } else {
        if (quarter < 3) conv2_refl<8>(xb, rq, dst);
        else             conv2_refl<9>(xb, rq, dst);
    }
    __syncthreads();

    // interp: outputs s with i0 in [r0, r0+31]; float4 across 128 f; LDS-only
    const int nunits = cnt * (FL / 4);
    for (int u = tx; u < nunits; u += 256) {
        const int ui   = u >> 5;
        const int s    = s_lo + ui;
        const int col4 = u & 31;
        const int ro   = sm_ro[ui];
        const float fr = sm_fr[ui];
        const float om = 1.0f - fr;

        const float4 a = ((const float4*)(smrows + ro * FL))[col4];
        const float4 c = ((const float4*)(smrows + (ro + 1) * FL))[col4];
        float4 o;
        o.x = a.x * om + c.x * fr;
        o.y = a.y * om + c.y * fr;
        o.z = a.z * om + c.z * fr;
        o.w = a.w * om + c.w * fr;
        ((float4*)(out + ((size_t)(b * S + s) * F + f0)))[col4] = o;
    }
}

// ---------------- launch ----------------------------------------------------
extern "C" void kernel_launch(void* const* d_in, const int* in_sizes, int n_in,
                              void* d_out, int out_size) {
    const float* x  = (const float*)d_in[0];
    const float* W1 = (const float*)d_in[1];
    const float* b1 = (const float*)d_in[2];
    const float* W2 = (const float*)d_in[3];
    const float* b2 = (const float*)d_in[4];
    float* out = (float*)d_out;

    mlp_kernel<<<S / 128, 128>>>(W1, b1, W2, b2);
    // loss scalar is the last output element
    scan_kernel<<<1, WT>>>(out + (out_size - 1));

    dim3 gridF(NTILES, F / FL, B);
    fused_kernel<<<gridF, 256>>>(x, out);
}